// round 1
// baseline (speedup 1.0000x reference)
#include <cuda_runtime.h>
#include <cuda_bf16.h>

#define BATCH 256
#define PPAIR 1024
#define TPTS  100
#define NGRID 65536
#define KMAX  2

__global__ __launch_bounds__(256, 4)
void pl_kernel(const float* __restrict__ inputs,
               const int*   __restrict__ dim_idx,
               const int*   __restrict__ birth_loc,
               const int*   __restrict__ death_loc,
               float* __restrict__ land,    // [B, 2, T, 2]
               float* __restrict__ trange)  // [B, 4]
{
    __shared__ float2 pairs[2][PPAIR];   // compacted (mid, half) per dim
    __shared__ int    s_dim[PPAIR];
    __shared__ float  s_b[PPAIR], s_d[PPAIR];
    __shared__ int    s_cnt[2];
    __shared__ float  s_tmin[2], s_tmax[2];
    __shared__ unsigned s_max[2];

    const int b   = blockIdx.x;
    const int tid = threadIdx.x;
    if (tid < 2) { s_cnt[tid] = 0; s_max[tid] = 0u; }
    __syncthreads();

    const float* __restrict__ row = inputs + (size_t)b * NGRID;
    const int* __restrict__ di = dim_idx   + b * PPAIR;
    const int* __restrict__ bl = birth_loc + b * PPAIR;
    const int* __restrict__ dl = death_loc + b * PPAIR;

    // Phase 1: gather + per-dim compaction (order irrelevant for top-k)
    #pragma unroll
    for (int k = 0; k < PPAIR / 256; k++) {
        int p = tid + k * 256;
        int d = di[p];
        float vb = __ldg(row + bl[p]);
        float vd = __ldg(row + dl[p]);
        s_dim[p] = d; s_b[p] = vb; s_d[p] = vd;
        int slot = atomicAdd(&s_cnt[d], 1);
        pairs[d][slot] = make_float2(0.5f * (vb + vd),   // mid
                                     0.5f * (vd - vb));  // half-width
    }
    __syncthreads();

    // t-range from the FIRST KMAX valid pairs in original order
    if (tid < 2) {
        const int dim = tid;
        float tmin = 1e30f, tmax = -1e30f;
        int found = 0;
        for (int p = 0; p < PPAIR && found < KMAX; p++) {
            if (s_dim[p] == dim) {
                tmin = fminf(tmin, s_b[p]);
                tmax = fmaxf(tmax, s_d[p]);
                found++;
            }
        }
        if (s_cnt[dim] == 0) { tmin = 0.0f; tmax = 0.0f; }
        s_tmin[dim] = tmin; s_tmax[dim] = tmax;
    }
    __syncthreads();

    // Phase 2: threads [0,128) -> dim 0, [128,256) -> dim 1 (warp-uniform)
    const int dim = tid >> 7;
    const int t   = tid & 127;
    if (t < TPTS) {
        const float tmin = s_tmin[dim];
        const float tmax = s_tmax[dim];
        const float tv   = tmin + (tmax - tmin) * ((float)t * (1.0f / (float)(TPTS - 1)));
        const int   cnt  = s_cnt[dim];
        const float2* __restrict__ pr = pairs[dim];

        float m1 = 0.0f, m2 = 0.0f;
        // tent(p,t) = half - |t - mid|; clamp to 0 implicit (m1,m2 >= 0)
        #pragma unroll 4
        for (int p = 0; p < cnt; p++) {
            float2 mh = pr[p];                  // broadcast LDS.64
            float v = mh.y - fabsf(tv - mh.x);
            m2 = fmaxf(m2, fminf(m1, v));
            m1 = fmaxf(m1, v);
        }
        size_t o = ((size_t)(b * 2 + dim) * TPTS + t) * 2;
        land[o]     = m1;
        land[o + 1] = m2;
        atomicMax(&s_max[dim], __float_as_uint(m1));  // m1 >= 0: bit-compare OK
    }
    __syncthreads();

    if (tid < 2) {
        bool nz = (s_cnt[tid] > 0) && (__uint_as_float(s_max[tid]) > 0.0f);
        trange[b * 4 + 2 * tid + 0] = nz ? s_tmin[tid] : 0.0f;
        trange[b * 4 + 2 * tid + 1] = nz ? s_tmax[tid] : 0.0f;
    }
}

extern "C" void kernel_launch(void* const* d_in, const int* in_sizes, int n_in,
                              void* d_out, int out_size) {
    const float* inputs    = (const float*)d_in[0];
    const int*   dim_idx   = (const int*)  d_in[1];
    const int*   birth_loc = (const int*)  d_in[2];
    const int*   death_loc = (const int*)  d_in[3];

    float* land   = (float*)d_out;                        // B*2*T*2 = 102400
    float* trange = land + (size_t)BATCH * 2 * TPTS * 2;  // B*4     = 1024

    pl_kernel<<<BATCH, 256>>>(inputs, dim_idx, birth_loc, death_loc, land, trange);
}

// round 2
// speedup vs baseline: 1.1364x; 1.1364x over previous
#include <cuda_runtime.h>
#include <cuda_bf16.h>

#define BATCH 256
#define PPAIR 1024
#define TPTS  100
#define NGRID 65536
#define KMAX  2

__global__ __launch_bounds__(1024, 2)
void pl_kernel(const float* __restrict__ inputs,
               const int*   __restrict__ dim_idx,
               const int*   __restrict__ birth_loc,
               const int*   __restrict__ death_loc,
               float* __restrict__ land,    // [B, 2, T, 2]
               float* __restrict__ trange)  // [B, 4]
{
    __shared__ float2 pairs[2][PPAIR];   // compacted (mid, half) per dim
    __shared__ int    s_dim[PPAIR];
    __shared__ float  s_b[PPAIR], s_d[PPAIR];
    __shared__ int    s_cnt[2];
    __shared__ float  s_tmin[2], s_tmax[2];
    __shared__ unsigned s_max[2];

    const int b    = blockIdx.x;
    const int tid  = threadIdx.x;
    const int lane = tid & 31;
    if (tid < 2) { s_cnt[tid] = 0; s_max[tid] = 0u; }
    __syncthreads();

    const float* __restrict__ row = inputs + (size_t)b * NGRID;

    // ---- Phase 1: gather + warp-aggregated per-dim compaction (1 pair/thread)
    {
        const int p  = tid;
        const int d  = dim_idx  [b * PPAIR + p];
        const float vb = __ldg(row + birth_loc[b * PPAIR + p]);
        const float vd = __ldg(row + death_loc[b * PPAIR + p]);
        s_dim[p] = d; s_b[p] = vb; s_d[p] = vd;

        unsigned mask1  = __ballot_sync(0xffffffffu, d == 1);
        unsigned mymask = d ? mask1 : ~mask1;
        unsigned lt     = (1u << lane) - 1u;
        int rank   = __popc(mymask & lt);
        int leader = __ffs(mymask) - 1;
        int base = 0;
        if (lane == leader) base = atomicAdd(&s_cnt[d], __popc(mymask));
        base = __shfl_sync(0xffffffffu, base, leader);
        pairs[d][base + rank] = make_float2(0.5f * (vb + vd),   // mid
                                            0.5f * (vd - vb));  // half-width
    }
    __syncthreads();

    // ---- t-range from the FIRST KMAX valid pairs in original order
    // (expected ~4 iterations; early exit)
    if (tid < 2) {
        const int dim = tid;
        float tmin = 1e30f, tmax = -1e30f;
        int found = 0;
        for (int p = 0; p < PPAIR && found < KMAX; p++) {
            if (s_dim[p] == dim) {
                tmin = fminf(tmin, s_b[p]);
                tmax = fmaxf(tmax, s_d[p]);
                found++;
            }
        }
        if (s_cnt[dim] == 0) { tmin = 0.0f; tmax = 0.0f; }
        s_tmin[dim] = tmin; s_tmax[dim] = tmax;
    }
    __syncthreads();

    // ---- Phase 2: 4 lanes per (dim, t) task; 2 pairs per iteration
    const int sub  = tid & 3;
    const int task = tid >> 2;       // 0..255
    const int dim  = task >> 7;      // warp-uniform (tid >> 9)
    const int t    = task & 127;

    float m1 = 0.0f, m2 = 0.0f;
    const int cnt = s_cnt[dim];

    if (t < TPTS) {
        const float tmin = s_tmin[dim];
        const float tmax = s_tmax[dim];
        const float tv   = tmin + (tmax - tmin) *
                           ((float)t * (1.0f / (float)(TPTS - 1)));

        const float4* __restrict__ p4 = (const float4*)pairs[dim];
        const int n4 = cnt >> 1;
        float m1b = 0.0f, m2b = 0.0f;
        // tent(p,t) = half - |t - mid|; clamp-to-0 implicit (accums start at 0)
        for (int i = sub; i < n4; i += 4) {
            float4 q  = p4[i];                       // two (mid,half) pairs
            float va  = q.y - fabsf(tv - q.x);
            float vb2 = q.w - fabsf(tv - q.z);
            m2  = fmaxf(m2,  fminf(m1,  va));  m1  = fmaxf(m1,  va);
            m2b = fmaxf(m2b, fminf(m1b, vb2)); m1b = fmaxf(m1b, vb2);
        }
        if ((cnt & 1) && sub == 0) {                 // odd tail pair
            float2 mh = pairs[dim][cnt - 1];
            float v = mh.y - fabsf(tv - mh.x);
            m2 = fmaxf(m2, fminf(m1, v)); m1 = fmaxf(m1, v);
        }
        // merge the two accumulator chains
        float lo = fminf(m1, m1b);
        m1 = fmaxf(m1, m1b);
        m2 = fmaxf(lo, fmaxf(m2, m2b));
    }

    // top-2 butterfly merge across the 4 sub-lanes of each task
    #pragma unroll
    for (int off = 1; off <= 2; off <<= 1) {
        float o1 = __shfl_xor_sync(0xffffffffu, m1, off);
        float o2 = __shfl_xor_sync(0xffffffffu, m2, off);
        float lo = fminf(m1, o1);
        m1 = fmaxf(m1, o1);
        m2 = fmaxf(lo, fmaxf(m2, o2));
    }

    if (t < TPTS && sub == 0) {
        float2 out = make_float2(m1, m2);
        *(float2*)&land[((size_t)(b * 2 + dim) * TPTS + t) * 2] = out;
    }

    // block-wide nonzero flag: one shared atomic per warp (m1 >= 0 -> bit order OK)
    unsigned wmax = __reduce_max_sync(0xffffffffu, __float_as_uint(m1));
    if (lane == 0) atomicMax(&s_max[dim], wmax);
    __syncthreads();

    if (tid < 2) {
        bool nz = (s_cnt[tid] > 0) && (__uint_as_float(s_max[tid]) > 0.0f);
        trange[b * 4 + 2 * tid + 0] = nz ? s_tmin[tid] : 0.0f;
        trange[b * 4 + 2 * tid + 1] = nz ? s_tmax[tid] : 0.0f;
    }
}

extern "C" void kernel_launch(void* const* d_in, const int* in_sizes, int n_in,
                              void* d_out, int out_size) {
    const float* inputs    = (const float*)d_in[0];
    const int*   dim_idx   = (const int*)  d_in[1];
    const int*   birth_loc = (const int*)  d_in[2];
    const int*   death_loc = (const int*)  d_in[3];

    float* land   = (float*)d_out;                        // B*2*T*2 = 102400
    float* trange = land + (size_t)BATCH * 2 * TPTS * 2;  // B*4     = 1024

    pl_kernel<<<BATCH, 1024>>>(inputs, dim_idx, birth_loc, death_loc, land, trange);
}